// round 9
// baseline (speedup 1.0000x reference)
#include <cuda_runtime.h>

#define BATCH 8
#define DIM 256
#define SEQ 16384
#define KK 3
#define HID 85
#define OUTC (DIM*KK)
#define BN_EPS 1e-5f
#define FULLM 0xffffffffu

#define NTHR 512
#define NCTA (BATCH*DIM)          // 2048, one CTA per (b,c) row
#define F4ROW (SEQ/4)             // 4096
#define F4THR (F4ROW/NTHR)        // 8
#define SMEM_BYTES (SEQ*4)        // 65536: whole row staged in smem

// Device globals (zero-initialized; self-resetting => graph-replay-safe)
__device__ float g_pooled[BATCH * DIM];
__device__ float g_w[BATCH * OUTC];
__device__ unsigned g_cnt[BATCH];
__device__ unsigned g_done[BATCH];
__device__ int g_ready[BATCH];

__global__ void __launch_bounds__(NTHR, 2)
fused_kernel(const float* __restrict__ x,
             const float* __restrict__ w1,
             const float* __restrict__ gamma,
             const float* __restrict__ beta,
             const float* __restrict__ mean,
             const float* __restrict__ var,
             const float* __restrict__ w2,
             const float* __restrict__ b2,
             const float* __restrict__ bias,
             float* __restrict__ out) {
    extern __shared__ float srow[];          // 16384 floats = this CTA's x row
    float4* srow4 = (float4*)srow;

    const int bid = blockIdx.x;
    const int b = bid >> 8;                  // batch
    const int c = bid & 255;                 // channel
    const int tid = threadIdx.x;
    const int lane = tid & 31;
    const size_t rowoff = (size_t)bid * SEQ;

    __shared__ float sm[16];
    __shared__ int sh_mlp;
    __shared__ float ps[DIM];
    __shared__ float ys[HID];
    __shared__ float wsh[4];

    // ---------- Phase 1: load row ONCE, pool it, stage into smem ----------
    float4 v[F4THR];
    #pragma unroll
    for (int j = 0; j < F4THR; j++)
        v[j] = *(const float4*)(x + rowoff + (size_t)(j * NTHR + tid) * 4);

    float s = 0.f;
    #pragma unroll
    for (int j = 0; j < F4THR; j++) {
        s += (v[j].x + v[j].y) + (v[j].z + v[j].w);
        srow4[j * NTHR + tid] = v[j];
    }

    #pragma unroll
    for (int off = 16; off > 0; off >>= 1)
        s += __shfl_down_sync(FULLM, s, off);
    if (lane == 0) sm[tid >> 5] = s;
    __syncthreads();
    if (tid == 0) {
        float t = 0.f;
        #pragma unroll
        for (int w = 0; w < 16; w++) t += sm[w];
        g_pooled[bid] = t * (1.f / SEQ);
        __threadfence();                                 // release pooled row
        unsigned r = atomicAdd(&g_cnt[b], 1u);
        sh_mlp = (r == DIM - 1);
    }
    __syncthreads();

    // ---------- Phase 2: last pool finisher of batch b runs the MLP -------
    if (sh_mlp) {
        __threadfence();                                 // acquire pooled[b]
        if (tid < DIM) ps[tid] = __ldcg(g_pooled + b * DIM + tid);
        __syncthreads();
        if (tid < HID) {
            const float* wr = w1 + tid * DIM;
            float acc = 0.f;
            #pragma unroll 8
            for (int k = 0; k < DIM; k++) acc = fmaf(__ldg(wr + k), ps[k], acc);
            float y = (acc - mean[tid]) * (gamma[tid] * rsqrtf(var[tid] + BN_EPS)) + beta[tid];
            ys[tid] = fmaxf(y, 0.f);
        }
        __syncthreads();
        #pragma unroll
        for (int rep = 0; rep < 2; rep++) {
            const int o = rep * NTHR + tid;              // 2*512 covers 768
            if (o < OUTC) {
                const float* wr = w2 + o * HID;
                float acc = b2[o];
                #pragma unroll 5
                for (int h = 0; h < HID; h++) acc = fmaf(__ldg(wr + h), ys[h], acc);
                g_w[b * OUTC + o] = acc;
            }
        }
        __syncthreads();
        if (tid == 0) {
            __threadfence();                             // release g_w[b]
            atomicExch(&g_ready[b], 1);
        }
    }

    // ---------- Phase 3: wait for weights, conv from SMEM, stream out -----
    if (tid == 0) {
        while (((volatile int*)g_ready)[b] == 0) __nanosleep(128);
    }
    __syncthreads();
    __threadfence();                                     // acquire g_w[b]

    if (tid < 3) wsh[tid] = __ldcg(g_w + b * OUTC + c * KK + tid);
    if (tid == 3) wsh[3] = __ldg(bias + c);
    __syncthreads();
    const float w0 = wsh[0], w1v = wsh[1], w2v = wsh[2], bb = wsh[3];

    #pragma unroll
    for (int j = 0; j < F4THR; j++) {
        const int p = j * NTHR + tid;                    // float4 index
        const int t = p * 4;
        const float4 xc = srow4[p];
        const float xl = (t == 0)       ? 0.f : srow[t - 1];
        const float xr = (t + 4 >= SEQ) ? 0.f : srow[t + 4];

        float4 o;
        o.x = fmaf(w0, xl,   fmaf(w1v, xc.x, fmaf(w2v, xc.y, bb)));
        o.y = fmaf(w0, xc.x, fmaf(w1v, xc.y, fmaf(w2v, xc.z, bb)));
        o.z = fmaf(w0, xc.y, fmaf(w1v, xc.z, fmaf(w2v, xc.w, bb)));
        o.w = fmaf(w0, xc.z, fmaf(w1v, xc.w, fmaf(w2v, xr,   bb)));

        __stcs((float4*)(out + rowoff + t), o);
    }

    // ---------- Reset counters for next graph replay ----------------------
    __syncthreads();
    if (tid == 0) {
        unsigned d = atomicAdd(&g_done[b], 1u);
        if (d == DIM - 1) {                              // last conv of batch b
            g_cnt[b] = 0;
            g_done[b] = 0;
            __threadfence();
            atomicExch(&g_ready[b], 0);
        }
    }
}

// ---------------------------------------------------------------------------
// Launch. Inputs (metadata order): x, w1, bn_gamma, bn_beta, bn_mean, bn_var,
// w2, b2, bias. Output: fp32 [8, 256, 16384].
// ---------------------------------------------------------------------------
extern "C" void kernel_launch(void* const* d_in, const int* in_sizes, int n_in,
                              void* d_out, int out_size) {
    const float* x     = (const float*)d_in[0];
    const float* w1    = (const float*)d_in[1];
    const float* gamma = (const float*)d_in[2];
    const float* beta  = (const float*)d_in[3];
    const float* mean  = (const float*)d_in[4];
    const float* var   = (const float*)d_in[5];
    const float* w2    = (const float*)d_in[6];
    const float* b2    = (const float*)d_in[7];
    const float* bias  = (const float*)d_in[8];
    float* out = (float*)d_out;

    cudaFuncSetAttribute(fused_kernel,
                         cudaFuncAttributeMaxDynamicSharedMemorySize, SMEM_BYTES);
    fused_kernel<<<NCTA, NTHR, SMEM_BYTES>>>(x, w1, gamma, beta, mean, var,
                                             w2, b2, bias, out);
}

// round 10
// speedup vs baseline: 3.2106x; 3.2106x over previous
#include <cuda_runtime.h>

#define BATCH 8
#define DIM 256
#define SEQ 16384
#define KK 3
#define HID 85
#define OUTC (DIM*KK)
#define BN_EPS 1e-5f
#define FULLM 0xffffffffu

// Scratch (device globals — no allocation allowed)
__device__ float g_pooled[BATCH * DIM];
__device__ float g_w[BATCH * OUTC];

// ---------------------------------------------------------------------------
// Kernel 1: mean over seq for each (b, c) row. grid=(DIM, BATCH), block=512.
// 8 front-batched float4 loads per thread. (Best measured: 5.9 TB/s.)
// ---------------------------------------------------------------------------
__global__ void pool_kernel(const float* __restrict__ x) {
    const int c = blockIdx.x;
    const int b = blockIdx.y;
    const size_t rowoff = ((size_t)b * DIM + c) * SEQ;
    const float4* row = (const float4*)(x + rowoff);

    float4 v[8];
    #pragma unroll
    for (int j = 0; j < 8; j++)
        v[j] = row[threadIdx.x + j * 512];

    float s = 0.f;
    #pragma unroll
    for (int j = 0; j < 8; j++)
        s += (v[j].x + v[j].y) + (v[j].z + v[j].w);

    #pragma unroll
    for (int off = 16; off > 0; off >>= 1)
        s += __shfl_down_sync(FULLM, s, off);

    __shared__ float sm[16];
    if ((threadIdx.x & 31) == 0) sm[threadIdx.x >> 5] = s;
    __syncthreads();
    if (threadIdx.x < 16) {
        float t = sm[threadIdx.x];
        #pragma unroll
        for (int off = 8; off > 0; off >>= 1)
            t += __shfl_down_sync(0xffffu, t, off);
        if (threadIdx.x == 0) g_pooled[b * DIM + c] = t * (1.f / SEQ);
    }
}

// ---------------------------------------------------------------------------
// Kernel 2: tiny MLP. grid=(16, BATCH), block=128 -> 128 blocks.
// Each block redundantly computes y[HID], then 48 of the 768 outputs.
// 4x more CTAs than before to hide the w2 DRAM latency.
// ---------------------------------------------------------------------------
__global__ void mlp_kernel(const float* __restrict__ w1,
                           const float* __restrict__ gamma,
                           const float* __restrict__ beta,
                           const float* __restrict__ mean,
                           const float* __restrict__ var,
                           const float* __restrict__ w2,
                           const float* __restrict__ b2) {
    const int b = blockIdx.y;
    const int chunk = blockIdx.x;          // 0..15, 48 outputs each
    const int tid = threadIdx.x;           // 0..127

    __shared__ float ps[DIM];
    __shared__ float ys[HID];

    ps[tid] = g_pooled[b * DIM + tid];
    ps[tid + 128] = g_pooled[b * DIM + tid + 128];
    __syncthreads();

    if (tid < HID) {
        const float* wr = w1 + tid * DIM;
        float acc = 0.f;
        #pragma unroll 8
        for (int c = 0; c < DIM; c++) acc = fmaf(__ldg(wr + c), ps[c], acc);
        float v = (acc - mean[tid]) * (gamma[tid] * rsqrtf(var[tid] + BN_EPS)) + beta[tid];
        ys[tid] = fmaxf(v, 0.f);
    }
    __syncthreads();

    const int o = chunk * 48 + (tid & 63);         // 64 lanes cover 48 outputs
    if ((tid & 63) < 48 && tid < 64) {             // only first 64 threads, 48 active
        const float* wr = w2 + o * HID;
        float acc = b2[o];
        #pragma unroll 5
        for (int h = 0; h < HID; h++) acc = fmaf(__ldg(wr + h), ys[h], acc);
        g_w[b * OUTC + o] = acc;
    }
}

// ---------------------------------------------------------------------------
// Kernel 3: depthwise 3-tap conv, pad=1, + bias. (R3-proven config)
// grid=(8, DIM, BATCH), block=256, 2 float4/thread, halo via warp shuffle,
// reversed traversal. x reads: __ldcs (evict-first, single-use).
// out stores: __stwt (write-through; no dirty L2 lines -> no cross-replay
// writeback contention against the next replay's pool reads).
// ---------------------------------------------------------------------------
__global__ void conv_kernel(const float* __restrict__ x,
                            const float* __restrict__ bias,
                            float* __restrict__ out) {
    const int b = (BATCH - 1) - blockIdx.z;
    const int c = (DIM - 1) - blockIdx.y;
    const int chunk = (int)(gridDim.x - 1) - blockIdx.x;     // 0..7
    const int tid = threadIdx.x;
    const int lane = tid & 31;
    const size_t rowoff = ((size_t)b * DIM + c) * SEQ;

    const float w0  = g_w[b * OUTC + c * KK + 0];
    const float w1v = g_w[b * OUTC + c * KK + 1];
    const float w2v = g_w[b * OUTC + c * KK + 2];
    const float bb  = __ldg(bias + c);

    const int p0 = chunk * 256 + tid;          // float4 idx, first half
    const int p1 = p0 + 2048;                  // second half
    const int t0 = p0 * 4;
    const int t1 = p1 * 4;

    const float4 xa = __ldcs((const float4*)(x + rowoff + t0));
    const float4 xb = __ldcs((const float4*)(x + rowoff + t1));

    float xla = __shfl_up_sync(FULLM, xa.w, 1);
    float xra = __shfl_down_sync(FULLM, xa.x, 1);
    float xlb = __shfl_up_sync(FULLM, xb.w, 1);
    float xrb = __shfl_down_sync(FULLM, xb.x, 1);

    if (lane == 0) {
        xla = (t0 == 0) ? 0.f : __ldg(x + rowoff + t0 - 1);
        xlb = __ldg(x + rowoff + t1 - 1);
    }
    if (lane == 31) {
        xra = __ldg(x + rowoff + t0 + 4);
        xrb = (t1 + 4 >= SEQ) ? 0.f : __ldg(x + rowoff + t1 + 4);
    }

    float4 oa, ob;
    oa.x = fmaf(w0, xla,  fmaf(w1v, xa.x, fmaf(w2v, xa.y, bb)));
    oa.y = fmaf(w0, xa.x, fmaf(w1v, xa.y, fmaf(w2v, xa.z, bb)));
    oa.z = fmaf(w0, xa.y, fmaf(w1v, xa.z, fmaf(w2v, xa.w, bb)));
    oa.w = fmaf(w0, xa.z, fmaf(w1v, xa.w, fmaf(w2v, xra,  bb)));

    ob.x = fmaf(w0, xlb,  fmaf(w1v, xb.x, fmaf(w2v, xb.y, bb)));
    ob.y = fmaf(w0, xb.x, fmaf(w1v, xb.y, fmaf(w2v, xb.z, bb)));
    ob.z = fmaf(w0, xb.y, fmaf(w1v, xb.z, fmaf(w2v, xb.w, bb)));
    ob.w = fmaf(w0, xb.z, fmaf(w1v, xb.w, fmaf(w2v, xrb,  bb)));

    __stwt((float4*)(out + rowoff + t0), oa);
    __stwt((float4*)(out + rowoff + t1), ob);
}

// ---------------------------------------------------------------------------
// Launch. Inputs (metadata order): x, w1, bn_gamma, bn_beta, bn_mean, bn_var,
// w2, b2, bias. Output: fp32 [8, 256, 16384].
// ---------------------------------------------------------------------------
extern "C" void kernel_launch(void* const* d_in, const int* in_sizes, int n_in,
                              void* d_out, int out_size) {
    const float* x     = (const float*)d_in[0];
    const float* w1    = (const float*)d_in[1];
    const float* gamma = (const float*)d_in[2];
    const float* beta  = (const float*)d_in[3];
    const float* mean  = (const float*)d_in[4];
    const float* var   = (const float*)d_in[5];
    const float* w2    = (const float*)d_in[6];
    const float* b2    = (const float*)d_in[7];
    const float* bias  = (const float*)d_in[8];
    float* out = (float*)d_out;

    dim3 pg(DIM, BATCH);
    pool_kernel<<<pg, 512>>>(x);

    dim3 mg(16, BATCH);
    mlp_kernel<<<mg, 128>>>(w1, gamma, beta, mean, var, w2, b2);

    dim3 cg(8, DIM, BATCH);
    conv_kernel<<<cg, 256>>>(x, bias, out);
}

// round 11
// speedup vs baseline: 3.3894x; 1.0557x over previous
#include <cuda_runtime.h>

#define BATCH 8
#define DIM 256
#define SEQ 16384
#define KK 3
#define HID 85
#define OUTC (DIM*KK)
#define BN_EPS 1e-5f
#define FULLM 0xffffffffu

#define W1_F4 ((HID*DIM*4)/16)    // 5440 float4s in w1
#define W2_F4 ((OUTC*HID*4)/16)   // 16320 float4s in w2

// Scratch (device globals — no allocation allowed)
__device__ float g_pooled[BATCH * DIM];
__device__ float g_w[BATCH * OUTC];

// ---------------------------------------------------------------------------
// Kernel 1: mean over seq for each (b, c) row. grid=(DIM, BATCH), block=512.
// 8 front-batched float4 loads per thread (proven 5.8-5.9 TB/s config).
// Extras vs R3:
//  - threads 0-11 prefetch 192B of w1/w2 into L2 (__ldcg) so the mlp kernel
//    hits L2 instead of cold DRAM. 2048 CTAs x 192B = 393KB covers both.
//  - x reads use __ldcs (evict-first): the single-use x stream then does not
//    evict the prefetched weights from L2.
// ---------------------------------------------------------------------------
__global__ void pool_kernel(const float* __restrict__ x,
                            const float* __restrict__ w1,
                            const float* __restrict__ w2) {
    const int c = blockIdx.x;
    const int b = blockIdx.y;
    const int tid = threadIdx.x;
    const int bid = b * DIM + c;
    const size_t rowoff = (size_t)bid * SEQ;
    const float4* row = (const float4*)(x + rowoff);

    // ---- L2 prefetch of mlp weights (no-op for tid >= 12) ----
    if (tid < 3) {
        const int i = bid * 3 + tid;
        if (i < W1_F4) {
            float4 p = __ldcg(((const float4*)w1) + i);
            asm volatile("" :: "f"(p.x), "f"(p.y), "f"(p.z), "f"(p.w));
        }
    } else if (tid < 12) {
        const int i = bid * 9 + (tid - 3);
        if (i < W2_F4) {
            float4 p = __ldcg(((const float4*)w2) + i);
            asm volatile("" :: "f"(p.x), "f"(p.y), "f"(p.z), "f"(p.w));
        }
    }

    // ---- row mean: 8 front-batched streaming float4 loads ----
    float4 v[8];
    #pragma unroll
    for (int j = 0; j < 8; j++)
        v[j] = __ldcs(row + tid + j * 512);

    float s = 0.f;
    #pragma unroll
    for (int j = 0; j < 8; j++)
        s += (v[j].x + v[j].y) + (v[j].z + v[j].w);

    #pragma unroll
    for (int off = 16; off > 0; off >>= 1)
        s += __shfl_down_sync(FULLM, s, off);

    __shared__ float sm[16];
    if ((tid & 31) == 0) sm[tid >> 5] = s;
    __syncthreads();
    if (tid < 16) {
        float t = sm[tid];
        #pragma unroll
        for (int off = 8; off > 0; off >>= 1)
            t += __shfl_down_sync(0xffffu, t, off);
        if (tid == 0) g_pooled[bid] = t * (1.f / SEQ);
    }
}

// ---------------------------------------------------------------------------
// Kernel 2: tiny MLP. grid=(4, BATCH), block=256. (R3-exact; weights now L2-hot)
// ---------------------------------------------------------------------------
__global__ void mlp_kernel(const float* __restrict__ w1,
                           const float* __restrict__ gamma,
                           const float* __restrict__ beta,
                           const float* __restrict__ mean,
                           const float* __restrict__ var,
                           const float* __restrict__ w2,
                           const float* __restrict__ b2) {
    const int b = blockIdx.y;
    const int chunk = blockIdx.x;          // 0..3, 192 outputs each
    const int tid = threadIdx.x;

    __shared__ float ps[DIM];
    __shared__ float ys[HID];

    ps[tid] = g_pooled[b * DIM + tid];
    __syncthreads();

    if (tid < HID) {
        const float* wr = w1 + tid * DIM;
        float acc = 0.f;
        #pragma unroll 8
        for (int c = 0; c < DIM; c++) acc = fmaf(wr[c], ps[c], acc);
        float v = (acc - mean[tid]) * (gamma[tid] * rsqrtf(var[tid] + BN_EPS)) + beta[tid];
        ys[tid] = fmaxf(v, 0.f);
    }
    __syncthreads();

    const int o = chunk * 192 + tid;
    if (tid < 192) {
        const float* wr = w2 + o * HID;
        float acc = b2[o];
        #pragma unroll 5
        for (int h = 0; h < HID; h++) acc = fmaf(wr[h], ys[h], acc);
        g_w[b * OUTC + o] = acc;
    }
}

// ---------------------------------------------------------------------------
// Kernel 3: depthwise 3-tap conv, pad=1, + bias. (R3-exact champion config)
// grid=(8, DIM, BATCH), block=256, 2 float4/thread, halo via warp shuffle,
// reversed traversal, __stcs stores.
// ---------------------------------------------------------------------------
__global__ void conv_kernel(const float* __restrict__ x,
                            const float* __restrict__ bias,
                            float* __restrict__ out) {
    const int b = (BATCH - 1) - blockIdx.z;
    const int c = (DIM - 1) - blockIdx.y;
    const int chunk = (int)(gridDim.x - 1) - blockIdx.x;     // 0..7
    const int tid = threadIdx.x;
    const int lane = tid & 31;
    const size_t rowoff = ((size_t)b * DIM + c) * SEQ;

    const float w0  = g_w[b * OUTC + c * KK + 0];
    const float w1v = g_w[b * OUTC + c * KK + 1];
    const float w2v = g_w[b * OUTC + c * KK + 2];
    const float bb  = __ldg(bias + c);

    const int p0 = chunk * 256 + tid;          // float4 idx, first half
    const int p1 = p0 + 2048;                  // second half
    const int t0 = p0 * 4;
    const int t1 = p1 * 4;

    const float4 xa = *(const float4*)(x + rowoff + t0);
    const float4 xb = *(const float4*)(x + rowoff + t1);

    float xla = __shfl_up_sync(FULLM, xa.w, 1);
    float xra = __shfl_down_sync(FULLM, xa.x, 1);
    float xlb = __shfl_up_sync(FULLM, xb.w, 1);
    float xrb = __shfl_down_sync(FULLM, xb.x, 1);

    if (lane == 0) {
        xla = (t0 == 0) ? 0.f : __ldg(x + rowoff + t0 - 1);
        xlb = __ldg(x + rowoff + t1 - 1);
    }
    if (lane == 31) {
        xra = __ldg(x + rowoff + t0 + 4);
        xrb = (t1 + 4 >= SEQ) ? 0.f : __ldg(x + rowoff + t1 + 4);
    }

    float4 oa, ob;
    oa.x = fmaf(w0, xla,  fmaf(w1v, xa.x, fmaf(w2v, xa.y, bb)));
    oa.y = fmaf(w0, xa.x, fmaf(w1v, xa.y, fmaf(w2v, xa.z, bb)));
    oa.z = fmaf(w0, xa.y, fmaf(w1v, xa.z, fmaf(w2v, xa.w, bb)));
    oa.w = fmaf(w0, xa.z, fmaf(w1v, xa.w, fmaf(w2v, xra,  bb)));

    ob.x = fmaf(w0, xlb,  fmaf(w1v, xb.x, fmaf(w2v, xb.y, bb)));
    ob.y = fmaf(w0, xb.x, fmaf(w1v, xb.y, fmaf(w2v, xb.z, bb)));
    ob.z = fmaf(w0, xb.y, fmaf(w1v, xb.z, fmaf(w2v, xb.w, bb)));
    ob.w = fmaf(w0, xb.z, fmaf(w1v, xb.w, fmaf(w2v, xrb,  bb)));

    __stcs((float4*)(out + rowoff + t0), oa);
    __stcs((float4*)(out + rowoff + t1), ob);
}

// ---------------------------------------------------------------------------
// Launch. Inputs (metadata order): x, w1, bn_gamma, bn_beta, bn_mean, bn_var,
// w2, b2, bias. Output: fp32 [8, 256, 16384].
// ---------------------------------------------------------------------------
extern "C" void kernel_launch(void* const* d_in, const int* in_sizes, int n_in,
                              void* d_out, int out_size) {
    const float* x     = (const float*)d_in[0];
    const float* w1    = (const float*)d_in[1];
    const float* gamma = (const float*)d_in[2];
    const float* beta  = (const float*)d_in[3];
    const float* mean  = (const float*)d_in[4];
    const float* var   = (const float*)d_in[5];
    const float* w2    = (const float*)d_in[6];
    const float* b2    = (const float*)d_in[7];
    const float* bias  = (const float*)d_in[8];
    float* out = (float*)d_out;

    dim3 pg(DIM, BATCH);
    pool_kernel<<<pg, 512>>>(x, w1, w2);

    dim3 mg(4, BATCH);
    mlp_kernel<<<mg, 256>>>(w1, gamma, beta, mean, var, w2, b2);

    dim3 cg(8, DIM, BATCH);
    conv_kernel<<<cg, 256>>>(x, bias, out);
}

// round 12
// speedup vs baseline: 3.4663x; 1.0227x over previous
#include <cuda_runtime.h>

#define BATCH 8
#define DIM 256
#define SEQ 16384
#define KK 3
#define HID 85
#define OUTC (DIM*KK)
#define BN_EPS 1e-5f
#define FULLM 0xffffffffu

// Scratch (device globals — no allocation allowed)
__device__ float g_pooled[BATCH * DIM];
__device__ float g_w[BATCH * OUTC];

// ---------------------------------------------------------------------------
// Kernel 1: mean over seq for each (b, c) row. grid=(DIM, BATCH), block=512.
// 8 front-batched float4 loads per thread (proven 5.8-5.9 TB/s config).
// ---------------------------------------------------------------------------
__global__ void pool_kernel(const float* __restrict__ x) {
    const int c = blockIdx.x;
    const int b = blockIdx.y;
    const size_t rowoff = ((size_t)b * DIM + c) * SEQ;
    const float4* row = (const float4*)(x + rowoff);

    float4 v[8];
    #pragma unroll
    for (int j = 0; j < 8; j++)
        v[j] = row[threadIdx.x + j * 512];

    float s = 0.f;
    #pragma unroll
    for (int j = 0; j < 8; j++)
        s += (v[j].x + v[j].y) + (v[j].z + v[j].w);

    #pragma unroll
    for (int off = 16; off > 0; off >>= 1)
        s += __shfl_down_sync(FULLM, s, off);

    __shared__ float sm[16];
    if ((threadIdx.x & 31) == 0) sm[threadIdx.x >> 5] = s;
    __syncthreads();
    if (threadIdx.x < 16) {
        float t = sm[threadIdx.x];
        #pragma unroll
        for (int off = 8; off > 0; off >>= 1)
            t += __shfl_down_sync(0xffffu, t, off);
        if (threadIdx.x == 0) g_pooled[b * DIM + c] = t * (1.f / SEQ);
    }
}

// ---------------------------------------------------------------------------
// Kernel 2: tiny MLP. grid=(4, BATCH), block=256. PDL secondary:
// prefetch w1/w2 into L2 BEFORE gridsync (overlaps pool tail), then sync and
// compute. Weight loads after sync then hit L2.
// ---------------------------------------------------------------------------
__global__ void mlp_kernel(const float* __restrict__ w1,
                           const float* __restrict__ gamma,
                           const float* __restrict__ beta,
                           const float* __restrict__ mean,
                           const float* __restrict__ var,
                           const float* __restrict__ w2,
                           const float* __restrict__ b2) {
    const int b = blockIdx.y;
    const int chunk = blockIdx.x;          // 0..3, 192 outputs each
    const int tid = threadIdx.x;
    const int gthr = (b * 4 + chunk) * 256 + tid;   // 0..8191

    // ---- pre-sync: prefetch weights into L2 (independent of pool) ----
    {
        const float4* w1f4 = (const float4*)w1;     // 5440 f4
        const float4* w2f4 = (const float4*)w2;     // 16320 f4
        if (gthr < 5440) {
            float4 p = __ldcg(w1f4 + gthr);
            asm volatile("" :: "f"(p.x), "f"(p.y), "f"(p.z), "f"(p.w));
        }
        #pragma unroll
        for (int r = 0; r < 2; r++) {
            int i = r * 8192 + gthr;
            if (i < 16320) {
                float4 p = __ldcg(w2f4 + i);
                asm volatile("" :: "f"(p.x), "f"(p.y), "f"(p.z), "f"(p.w));
            }
        }
    }

    cudaGridDependencySynchronize();       // pool's g_pooled now visible

    __shared__ float ps[DIM];
    __shared__ float ys[HID];

    ps[tid] = g_pooled[b * DIM + tid];
    __syncthreads();

    if (tid < HID) {
        const float* wr = w1 + tid * DIM;
        float acc = 0.f;
        #pragma unroll 8
        for (int c = 0; c < DIM; c++) acc = fmaf(wr[c], ps[c], acc);
        float v = (acc - mean[tid]) * (gamma[tid] * rsqrtf(var[tid] + BN_EPS)) + beta[tid];
        ys[tid] = fmaxf(v, 0.f);
    }
    __syncthreads();

    const int o = chunk * 192 + tid;
    if (tid < 192) {
        const float* wr = w2 + o * HID;
        float acc = b2[o];
        #pragma unroll 5
        for (int h = 0; h < HID; h++) acc = fmaf(wr[h], ys[h], acc);
        g_w[b * OUTC + o] = acc;
    }
}

// ---------------------------------------------------------------------------
// Kernel 3: depthwise 3-tap conv. PDL secondary: ALL x loads + halo exchange
// happen BEFORE gridsync (overlapping pool/mlp tails and the previous
// writeback drain); only the g_w read and the output stores come after.
// grid=(8, DIM, BATCH), block=256, 2 float4/thread, __stcs stores.
// ---------------------------------------------------------------------------
__global__ void conv_kernel(const float* __restrict__ x,
                            const float* __restrict__ bias,
                            float* __restrict__ out) {
    const int b = (BATCH - 1) - blockIdx.z;
    const int c = (DIM - 1) - blockIdx.y;
    const int chunk = (int)(gridDim.x - 1) - blockIdx.x;     // 0..7
    const int tid = threadIdx.x;
    const int lane = tid & 31;
    const size_t rowoff = ((size_t)b * DIM + c) * SEQ;

    const int p0 = chunk * 256 + tid;          // float4 idx, first half
    const int p1 = p0 + 2048;                  // second half
    const int t0 = p0 * 4;
    const int t1 = p1 * 4;

    // ---- pre-sync: the entire x read for this thread ----
    const float4 xa = *(const float4*)(x + rowoff + t0);
    const float4 xb = *(const float4*)(x + rowoff + t1);
    const float bb = __ldg(bias + c);

    float xla = __shfl_up_sync(FULLM, xa.w, 1);
    float xra = __shfl_down_sync(FULLM, xa.x, 1);
    float xlb = __shfl_up_sync(FULLM, xb.w, 1);
    float xrb = __shfl_down_sync(FULLM, xb.x, 1);

    if (lane == 0) {
        xla = (t0 == 0) ? 0.f : __ldg(x + rowoff + t0 - 1);
        xlb = __ldg(x + rowoff + t1 - 1);
    }
    if (lane == 31) {
        xra = __ldg(x + rowoff + t0 + 4);
        xrb = (t1 + 4 >= SEQ) ? 0.f : __ldg(x + rowoff + t1 + 4);
    }

    cudaGridDependencySynchronize();           // mlp's g_w now visible

    const float w0  = g_w[b * OUTC + c * KK + 0];
    const float w1v = g_w[b * OUTC + c * KK + 1];
    const float w2v = g_w[b * OUTC + c * KK + 2];

    float4 oa, ob;
    oa.x = fmaf(w0, xla,  fmaf(w1v, xa.x, fmaf(w2v, xa.y, bb)));
    oa.y = fmaf(w0, xa.x, fmaf(w1v, xa.y, fmaf(w2v, xa.z, bb)));
    oa.z = fmaf(w0, xa.y, fmaf(w1v, xa.z, fmaf(w2v, xa.w, bb)));
    oa.w = fmaf(w0, xa.z, fmaf(w1v, xa.w, fmaf(w2v, xra,  bb)));

    ob.x = fmaf(w0, xlb,  fmaf(w1v, xb.x, fmaf(w2v, xb.y, bb)));
    ob.y = fmaf(w0, xb.x, fmaf(w1v, xb.y, fmaf(w2v, xb.z, bb)));
    ob.z = fmaf(w0, xb.y, fmaf(w1v, xb.z, fmaf(w2v, xb.w, bb)));
    ob.w = fmaf(w0, xb.z, fmaf(w1v, xb.w, fmaf(w2v, xrb,  bb)));

    __stcs((float4*)(out + rowoff + t0), oa);
    __stcs((float4*)(out + rowoff + t1), ob);
}

// ---------------------------------------------------------------------------
// Launch: pool normally; mlp and conv as PDL secondaries so their prologues
// overlap the predecessor's tail wave and drain.
// Inputs: x, w1, bn_gamma, bn_beta, bn_mean, bn_var, w2, b2, bias.
// ---------------------------------------------------------------------------
extern "C" void kernel_launch(void* const* d_in, const int* in_sizes, int n_in,
                              void* d_out, int out_size) {
    const float* x     = (const float*)d_in[0];
    const float* w1    = (const float*)d_in[1];
    const float* gamma = (const float*)d_in[2];
    const float* beta  = (const float*)d_in[3];
    const float* mean  = (const float*)d_in[4];
    const float* var   = (const float*)d_in[5];
    const float* w2    = (const float*)d_in[6];
    const float* b2    = (const float*)d_in[7];
    const float* bias  = (const float*)d_in[8];
    float* out = (float*)d_out;

    dim3 pg(DIM, BATCH);
    pool_kernel<<<pg, 512>>>(x);

    cudaLaunchAttribute attr[1];
    attr[0].id = cudaLaunchAttributeProgrammaticStreamSerialization;
    attr[0].val.programmaticStreamSerializationAllowed = 1;

    {
        cudaLaunchConfig_t cfg = {};
        cfg.gridDim = dim3(4, BATCH);
        cfg.blockDim = dim3(256);
        cfg.attrs = attr;
        cfg.numAttrs = 1;
        cudaLaunchKernelEx(&cfg, mlp_kernel, w1, gamma, beta, mean, var, w2, b2);
    }
    {
        cudaLaunchConfig_t cfg = {};
        cfg.gridDim = dim3(8, DIM, BATCH);
        cfg.blockDim = dim3(256);
        cfg.attrs = attr;
        cfg.numAttrs = 1;
        cudaLaunchKernelEx(&cfg, conv_kernel, x, bias, out);
    }
}